// round 2
// baseline (speedup 1.0000x reference)
#include <cuda_runtime.h>
#include <math.h>

#define B_ 16
#define D_ 128
#define N_ 8192
#define KS_ 5
#define NW_ 64
#define TQ 16

__device__ float g_wq[D_*KS_*D_];   // [(i*KS+t)*D + o]
__device__ float g_wk[D_*KS_*D_];
__device__ float g_wv[D_*KS_*D_];
__device__ float g_cs[N_*64];
__device__ float g_sn[N_*64];
__device__ float g_q[B_*N_*D_];     // (B,N,D), rotary+scaled
__device__ float g_k[B_*N_*D_];
__device__ float g_v[B_*N_*D_];
__device__ float g_a[B_*N_*D_];
__device__ float g_scale[D_];
__device__ float g_shift[D_];

// -------------------- prep --------------------
__global__ void prep_weights(const float* __restrict__ qw, const float* __restrict__ kw,
                             const float* __restrict__ vw) {
    int e = blockIdx.x * blockDim.x + threadIdx.x;
    if (e >= D_*KS_*D_) return;
    int o = e % D_, r = e / D_;
    int src = o * (D_*KS_) + r;
    g_wq[e] = qw[src]; g_wk[e] = kw[src]; g_wv[e] = vw[src];
}

__global__ void prep_trig() {
    int e = blockIdx.x * blockDim.x + threadIdx.x;
    if (e >= N_*64) return;
    int n = e >> 6, f = e & 63;
    double invf = pow(10000.0, -((double)(2*f)) / 128.0);
    float ang = (float)n * (float)invf;       // match JAX fp32 angle rounding
    double a = (double)ang;
    g_cs[e] = (float)cos(a);
    g_sn[e] = (float)sin(a);
}

// ---------- fused QKV causal conv + bias + rotary + scale ----------
__global__ __launch_bounds__(128) void qkv_conv(const float* __restrict__ x,
                                                const float* __restrict__ qb,
                                                const float* __restrict__ kb,
                                                const float* __restrict__ vb) {
    __shared__ float sm[4096];
    const int b = blockIdx.y, n0 = blockIdx.x * TQ, d = threadIdx.x;
    float* xs = sm;                                   // [128][20]
    int warp = d >> 5, lane = d & 31;
    for (int r = warp; r < 128; r += 4) {
        const float* xr = x + ((size_t)(b*D_ + r)) * N_;
        for (int c = lane; c < 20; c += 32) {
            int n = n0 - 4 + c;
            xs[r*20 + c] = (n >= 0) ? xr[n] : 0.0f;
        }
    }
    __syncthreads();

    float aq[TQ], ak[TQ], av[TQ];
#pragma unroll
    for (int j = 0; j < TQ; j++) { aq[j] = 0.f; ak[j] = 0.f; av[j] = 0.f; }

    for (int i = 0; i < 128; i++) {
        float wq[5], wk[5], wv[5];
#pragma unroll
        for (int t = 0; t < 5; t++) {
            int wi = (i*5 + t)*128 + d;
            wq[t] = g_wq[wi]; wk[t] = g_wk[wi]; wv[t] = g_wv[wi];
        }
#pragma unroll
        for (int c = 0; c < 20; c++) {
            float xv = xs[i*20 + c];
#pragma unroll
            for (int t = 0; t < 5; t++) {
                int j = c - t;
                if (j >= 0 && j < TQ) {
                    aq[j] = fmaf(wq[t], xv, aq[j]);
                    ak[j] = fmaf(wk[t], xv, ak[j]);
                    av[j] = fmaf(wv[t], xv, av[j]);
                }
            }
        }
    }
    __syncthreads();

    float* qsm = sm;            // [TQ][128]
    float* ksm = sm + 2048;     // [TQ][128]
    float bq = qb[d], bk = kb[d], bv = vb[d];
#pragma unroll
    for (int j = 0; j < TQ; j++) {
        qsm[j*128 + d] = aq[j] + bq;
        ksm[j*128 + d] = ak[j] + bk;
    }
    __syncthreads();

    const float scl = 0.08838834764831845f;  // 128^-0.5
    int dp = (d + 64) & 127;
    float sg = (d < 64) ? -1.0f : 1.0f;
    int f = d & 63;
    for (int j = 0; j < TQ; j++) {
        int n = n0 + j;
        float cc = g_cs[n*64 + f], ss = g_sn[n*64 + f];
        float qv = qsm[j*128 + d],      kv = ksm[j*128 + d];
        float qh = sg * qsm[j*128 + dp], kh = sg * ksm[j*128 + dp];
        size_t o = ((size_t)(b*N_ + n)) * 128 + d;
        g_q[o] = (qv*cc + qh*ss) * scl;
        g_k[o] = kv*cc + kh*ss;
        g_v[o] = av[j] + bv;
    }
}

// ---------------- windowed causal attention ----------------
#define QS 132
#define SS 260
#define ATTN_SMEM ((128*QS + 128*SS + 128*36) * 4)

__global__ __launch_bounds__(256) void attn_kernel() {
    extern __shared__ float sm[];
    float* qs = sm;                 // [128][132]
    float* S  = sm + 128*QS;        // [128][260]
    float* kv = S  + 128*SS;        // ksT [128][36] / vs [32][128]

    const int wi = blockIdx.x, b = blockIdx.y;
    const int n0 = wi * 128, t = threadIdx.x;

    for (int fidx = t; fidx < 4096; fidx += 256) {
        int r = fidx >> 5, c = fidx & 31;
        *(float4*)(qs + r*QS + c*4) =
            *(const float4*)(g_q + ((size_t)(b*N_ + n0 + r))*D_ + c*4);
    }

    // ---- S = q @ k^T, 8 chunks of 32 key rows ----
    {
        const int rg = t >> 3, cg = t & 7;
        const int r0 = rg*4, c0 = cg*4;
        for (int ch = 0; ch < 8; ch++) {
            __syncthreads();
            {
                int c = t & 31;
                int nk = n0 - 128 + ch*32 + c;
                const float* kr = g_k + ((size_t)(b*N_ + nk))*D_;
                for (int d4 = t >> 5; d4 < 32; d4 += 8) {
                    float4 v = make_float4(0.f,0.f,0.f,0.f);
                    if (nk >= 0) v = *(const float4*)(kr + d4*4);
                    kv[(d4*4+0)*36 + c] = v.x;
                    kv[(d4*4+1)*36 + c] = v.y;
                    kv[(d4*4+2)*36 + c] = v.z;
                    kv[(d4*4+3)*36 + c] = v.w;
                }
            }
            __syncthreads();
            float acc[4][4];
#pragma unroll
            for (int u = 0; u < 4; u++)
#pragma unroll
                for (int w2 = 0; w2 < 4; w2++) acc[u][w2] = 0.f;

            for (int d4 = 0; d4 < 32; d4++) {
                float4 q4[4];
#pragma unroll
                for (int rr = 0; rr < 4; rr++)
                    q4[rr] = *(const float4*)(qs + (r0+rr)*QS + d4*4);
#pragma unroll
                for (int j = 0; j < 4; j++) {
                    float4 k4 = *(const float4*)(kv + (d4*4+j)*36 + c0);
#pragma unroll
                    for (int rr = 0; rr < 4; rr++) {
                        float qv = (j==0)?q4[rr].x:(j==1)?q4[rr].y:(j==2)?q4[rr].z:q4[rr].w;
                        acc[rr][0] = fmaf(qv, k4.x, acc[rr][0]);
                        acc[rr][1] = fmaf(qv, k4.y, acc[rr][1]);
                        acc[rr][2] = fmaf(qv, k4.z, acc[rr][2]);
                        acc[rr][3] = fmaf(qv, k4.w, acc[rr][3]);
                    }
                }
            }
#pragma unroll
            for (int rr = 0; rr < 4; rr++)
                *(float4*)(S + (r0+rr)*SS + ch*32 + c0) =
                    make_float4(acc[rr][0], acc[rr][1], acc[rr][2], acc[rr][3]);
        }
    }
    __syncthreads();

    // ---- masked softmax, row i valid cols [jstart, 128+i] ----
    if (t < 128) {
        float* row = S + t*SS;
        int jstart = (wi == 0) ? 128 : 0;
        int jend = 128 + t + 1;
        float m = -3.402823466e38f;
        for (int j = jstart; j < jend; j++) m = fmaxf(m, row[j]);
        float sum = 0.f;
        for (int j = jstart; j < jend; j++) { float e = expf(row[j] - m); row[j] = e; sum += e; }
        float inv = 1.0f / sum;
        for (int j = 0; j < jstart; j++) row[j] = 0.f;
        for (int j = jstart; j < jend; j++) row[j] *= inv;
        for (int j = jend; j < 256; j++) row[j] = 0.f;
    }

    // ---- OUT = P @ V, 8 chunks ----
    {
        const int rg = t >> 4, cg = t & 15;
        const int r0 = rg*8, c0 = cg*8;
        float acc[8][8];
#pragma unroll
        for (int u = 0; u < 8; u++)
#pragma unroll
            for (int w2 = 0; w2 < 8; w2++) acc[u][w2] = 0.f;

        for (int ch = 0; ch < 8; ch++) {
            __syncthreads();
            for (int fidx = t; fidx < 1024; fidx += 256) {
                int r = fidx >> 5, c = fidx & 31;
                int nk = n0 - 128 + ch*32 + r;
                float4 v = make_float4(0.f,0.f,0.f,0.f);
                if (nk >= 0) v = *(const float4*)(g_v + ((size_t)(b*N_ + nk))*D_ + c*4);
                *(float4*)(kv + r*128 + c*4) = v;
            }
            __syncthreads();
            for (int k4 = 0; k4 < 8; k4++) {
                float4 p4[8];
#pragma unroll
                for (int rr = 0; rr < 8; rr++)
                    p4[rr] = *(const float4*)(S + (r0+rr)*SS + ch*32 + k4*4);
#pragma unroll
                for (int j = 0; j < 4; j++) {
                    float4 va = *(const float4*)(kv + (k4*4+j)*128 + c0);
                    float4 vb2 = *(const float4*)(kv + (k4*4+j)*128 + c0 + 4);
#pragma unroll
                    for (int rr = 0; rr < 8; rr++) {
                        float pv = (j==0)?p4[rr].x:(j==1)?p4[rr].y:(j==2)?p4[rr].z:p4[rr].w;
                        acc[rr][0] = fmaf(pv, va.x,  acc[rr][0]);
                        acc[rr][1] = fmaf(pv, va.y,  acc[rr][1]);
                        acc[rr][2] = fmaf(pv, va.z,  acc[rr][2]);
                        acc[rr][3] = fmaf(pv, va.w,  acc[rr][3]);
                        acc[rr][4] = fmaf(pv, vb2.x, acc[rr][4]);
                        acc[rr][5] = fmaf(pv, vb2.y, acc[rr][5]);
                        acc[rr][6] = fmaf(pv, vb2.z, acc[rr][6]);
                        acc[rr][7] = fmaf(pv, vb2.w, acc[rr][7]);
                    }
                }
            }
        }
#pragma unroll
        for (int rr = 0; rr < 8; rr++) {
            float* o = g_a + ((size_t)(b*N_ + n0 + r0 + rr))*D_ + c0;
            *(float4*)(o)   = make_float4(acc[rr][0], acc[rr][1], acc[rr][2], acc[rr][3]);
            *(float4*)(o+4) = make_float4(acc[rr][4], acc[rr][5], acc[rr][6], acc[rr][7]);
        }
    }
}

// ---------------- 1x1 conv -> d_out in (B,D,N) ----------------
#define C1_SMEM ((128*128 + 32*132) * 4)

__global__ __launch_bounds__(256) void conv1x1(const float* __restrict__ ow,
                                               const float* __restrict__ ob,
                                               float* __restrict__ out) {
    extern __shared__ float sm[];
    float* ws = sm;             // [128][128]
    float* as = sm + 16384;     // [32][132]
    const int b = blockIdx.y, n0 = blockIdx.x * 32, t = threadIdx.x;

    for (int f = t; f < 4096; f += 256) ((float4*)ws)[f] = ((const float4*)ow)[f];
    for (int f = t; f < 1024; f += 256) {
        int r = f >> 5, c = f & 31;
        *(float4*)(as + r*132 + c*4) =
            *(const float4*)(g_a + ((size_t)(b*N_ + n0 + r))*D_ + c*4);
    }
    __syncthreads();

    const int rg = t >> 4, cg = t & 15;
    const int o0 = rg*8, nA = cg*2;
    float acc[8][2];
#pragma unroll
    for (int u = 0; u < 8; u++) { acc[u][0] = 0.f; acc[u][1] = 0.f; }

    for (int i4 = 0; i4 < 32; i4++) {
        float4 a0 = *(const float4*)(as + nA*132 + i4*4);
        float4 a1 = *(const float4*)(as + (nA+1)*132 + i4*4);
#pragma unroll
        for (int rr = 0; rr < 8; rr++) {
            float4 w = *(const float4*)(ws + (o0+rr)*128 + i4*4);
            acc[rr][0] = fmaf(w.x, a0.x, acc[rr][0]);
            acc[rr][0] = fmaf(w.y, a0.y, acc[rr][0]);
            acc[rr][0] = fmaf(w.z, a0.z, acc[rr][0]);
            acc[rr][0] = fmaf(w.w, a0.w, acc[rr][0]);
            acc[rr][1] = fmaf(w.x, a1.x, acc[rr][1]);
            acc[rr][1] = fmaf(w.y, a1.y, acc[rr][1]);
            acc[rr][1] = fmaf(w.z, a1.z, acc[rr][1]);
            acc[rr][1] = fmaf(w.w, a1.w, acc[rr][1]);
        }
    }
#pragma unroll
    for (int rr = 0; rr < 8; rr++) {
        float bo = ob[o0 + rr];
        float* p = out + ((size_t)(b*D_ + o0 + rr))*N_ + n0 + nA;
        p[0] = acc[rr][0] + bo;
        p[1] = acc[rr][1] + bo;
    }
}

// ---------------- BatchNorm ----------------
__global__ void bn_stats(const float* __restrict__ y, const float* __restrict__ gamma,
                         const float* __restrict__ beta) {
    int d = blockIdx.x, t = threadIdx.x;
    double s = 0.0, s2 = 0.0;
    for (int b = 0; b < B_; b++) {
        const float* p = y + ((size_t)(b*D_ + d)) * N_;
        for (int n = t; n < N_; n += 256) { double v = p[n]; s += v; s2 += v*v; }
    }
    __shared__ double sh[512];
    sh[t] = s; sh[256 + t] = s2;
    __syncthreads();
    for (int o = 128; o > 0; o >>= 1) {
        if (t < o) { sh[t] += sh[t+o]; sh[256+t] += sh[256+t+o]; }
        __syncthreads();
    }
    if (t == 0) {
        double cnt = (double)B_ * (double)N_;
        double m = sh[0] / cnt;
        double var = sh[256] / cnt - m*m;
        double rs = rsqrt(var + 1e-5);
        double sc = rs * (double)gamma[d];
        g_scale[d] = (float)sc;
        g_shift[d] = (float)((double)beta[d] - m*sc);
    }
}

__global__ void bn_apply(float* __restrict__ y) {
    int i = (blockIdx.x * 256 + threadIdx.x) * 4;
    int d = (i >> 13) & 127;
    float sc = g_scale[d], sh = g_shift[d];
    float4 v = *(float4*)(y + i);
    v.x = v.x*sc + sh; v.y = v.y*sc + sh; v.z = v.z*sc + sh; v.w = v.w*sc + sh;
    *(float4*)(y + i) = v;
}

// ---------------- launch ----------------
extern "C" void kernel_launch(void* const* d_in, const int* in_sizes, int n_in,
                              void* d_out, int out_size) {
    const float* x  = (const float*)d_in[0];
    const float* qw = (const float*)d_in[1];
    const float* qb = (const float*)d_in[2];
    const float* kw = (const float*)d_in[3];
    const float* kb = (const float*)d_in[4];
    const float* vw = (const float*)d_in[5];
    const float* vb = (const float*)d_in[6];
    const float* ow = (const float*)d_in[7];
    const float* ob = (const float*)d_in[8];
    const float* gamma = (const float*)d_in[9];
    const float* beta  = (const float*)d_in[10];
    float* out = (float*)d_out;

    cudaFuncSetAttribute(attn_kernel, cudaFuncAttributeMaxDynamicSharedMemorySize, ATTN_SMEM);
    cudaFuncSetAttribute(conv1x1, cudaFuncAttributeMaxDynamicSharedMemorySize, C1_SMEM);

    prep_weights<<<(D_*KS_*D_ + 255) / 256, 256>>>(qw, kw, vw);
    prep_trig<<<(N_*64 + 255) / 256, 256>>>();
    qkv_conv<<<dim3(N_/TQ, B_), 128>>>(x, qb, kb, vb);
    attn_kernel<<<dim3(NW_, B_), 256, ATTN_SMEM>>>();
    conv1x1<<<dim3(N_/32, B_), 256, C1_SMEM>>>(ow, ob, out);
    bn_stats<<<D_, 256>>>(out, gamma, beta);
    bn_apply<<<(B_*D_*N_) / 1024, 256>>>(out);
}